// round 8
// baseline (speedup 1.0000x reference)
#include <cuda_runtime.h>

#define NN     50000
#define EE     1600000
#define IN_F   128
#define OUT_F  32
#define NT_    20
#define ET_    4
#define ETE_   16
#define EAE_   16
#define ED_    16
#define SLOPE  0.2f

// ---- scratch (device globals; allocation-free, zero-initialized) ----
__device__ float     g_hm[NN * OUT_F];   // 6.4 MB : h @ lin_W[0:32] (L2-resident)
__device__ float     g_att[NN * 4];      // 0.8 MB : {ai0, ai1, aj0, aj1}
__device__ long long g_erec[EE];         // 12.8 MB: dst-sorted {e, src|et<<16}
__device__ int       g_cnt[NN];          // zeroed by k_agg at end of every call
__device__ int       g_off[NN];
__device__ int       g_woff[NN];
__device__ int       g_bsum[64];

__device__ __forceinline__ float lrelu(float v) { return v > 0.f ? v : SLOPE * v; }

// ---- f32x2 packed helpers (Blackwell) ----
typedef unsigned long long u64t;
__device__ __forceinline__ u64t pk2(float lo, float hi) {
    u64t r; asm("mov.b64 %0, {%1, %2};" : "=l"(r) : "f"(lo), "f"(hi)); return r;
}
__device__ __forceinline__ void upk2(u64t v, float& lo, float& hi) {
    asm("mov.b64 {%0, %1}, %2;" : "=f"(lo), "=f"(hi) : "l"(v));
}
__device__ __forceinline__ u64t fma2(u64t a, u64t b, u64t c) {
    u64t d; asm("fma.rn.f32x2 %0, %1, %2, %3;" : "=l"(d) : "l"(a), "l"(b), "l"(c)); return d;
}
__device__ __forceinline__ u64t add2(u64t a, u64t b) {
    u64t d; asm("add.rn.f32x2 %0, %1, %2;" : "=l"(d) : "l"(a), "l"(b)); return d;
}

// ---------------------------------------------------------------------------
__global__ void k_cnt(const int* __restrict__ ei) {
    int e = blockIdx.x * blockDim.x + threadIdx.x;
    if (e < EE) atomicAdd(&g_cnt[ei[EE + e]], 1);
}

// ---------------------------------------------------------------------------
// HeteroLinear + node-side precomputes (h never leaves registers):
//   hm = h @ lin_W[0:32];  ai_h = h.att_W[0:32,h];  aj_h = h.att_W[32:64,h]
// ---------------------------------------------------------------------------
#define NPB 1024
__global__ void k_het(const float* __restrict__ x, const int* __restrict__ ntypes,
                      const float* __restrict__ het_W, const float* __restrict__ het_b,
                      const float* __restrict__ att_W, const float* __restrict__ lin_W) {
    __shared__ float Ws[IN_F * OUT_F];
    __shared__ float bs[OUT_F];
    __shared__ float aWs[64 * 2];
    __shared__ float lWs[OUT_F * OUT_F];
    __shared__ int   list[NPB];
    __shared__ int   cnt;

    const int t    = blockIdx.x;
    const int base = blockIdx.y * NPB;
    const int tid  = threadIdx.x;

    for (int i = tid; i < IN_F * OUT_F; i += blockDim.x) Ws[i] = het_W[t * IN_F * OUT_F + i];
    for (int i = tid; i < OUT_F * OUT_F; i += blockDim.x) lWs[i] = lin_W[i];
    if (tid < 128)   aWs[tid] = att_W[tid];
    if (tid < OUT_F) bs[tid] = het_b[t * OUT_F + tid];
    if (tid == 0)    cnt = 0;
    __syncthreads();

    const int end = min(base + NPB, NN);
    for (int n = base + tid; n < end; n += blockDim.x)
        if (ntypes[n] == t) { int p = atomicAdd(&cnt, 1); list[p] = n; }
    __syncthreads();

    const int lane = tid & 31, warp = tid >> 5, nw = blockDim.x >> 5;
    for (int i = warp; i < cnt; i += nw) {
        const int n = list[i];
        const float* xr = x + (size_t)n * IN_F;
        float x0 = xr[lane], x1 = xr[32 + lane], x2 = xr[64 + lane], x3 = xr[96 + lane];
        float acc = bs[lane];
        #pragma unroll
        for (int k = 0; k < 32; k++) {
            acc += __shfl_sync(0xffffffffu, x0, k) * Ws[ k        * OUT_F + lane];
            acc += __shfl_sync(0xffffffffu, x1, k) * Ws[(32 + k)  * OUT_F + lane];
            acc += __shfl_sync(0xffffffffu, x2, k) * Ws[(64 + k)  * OUT_F + lane];
            acc += __shfl_sync(0xffffffffu, x3, k) * Ws[(96 + k)  * OUT_F + lane];
        }
        float ai0 = acc * aWs[lane * 2 + 0], ai1 = acc * aWs[lane * 2 + 1];
        float aj0 = acc * aWs[64 + lane * 2 + 0], aj1 = acc * aWs[64 + lane * 2 + 1];
        #pragma unroll
        for (int o = 16; o > 0; o >>= 1) {
            ai0 += __shfl_xor_sync(0xffffffffu, ai0, o);
            ai1 += __shfl_xor_sync(0xffffffffu, ai1, o);
            aj0 += __shfl_xor_sync(0xffffffffu, aj0, o);
            aj1 += __shfl_xor_sync(0xffffffffu, aj1, o);
        }
        float hm = 0.f;
        #pragma unroll
        for (int k = 0; k < 32; k++)
            hm += __shfl_sync(0xffffffffu, acc, k) * lWs[k * OUT_F + lane];
        g_hm[n * OUT_F + lane] = hm;
        if (lane == 0)
            *reinterpret_cast<float4*>(&g_att[n * 4]) = make_float4(ai0, ai1, aj0, aj1);
    }
}

// ---------------------------------------------------------------------------
// Scan
// ---------------------------------------------------------------------------
__global__ void k_scan1() {
    __shared__ int ws[32];
    const int b = blockIdx.x, tid = threadIdx.x;
    const int i = b * 1024 + tid;
    int v = (i < NN) ? g_cnt[i] : 0;
    const int lane = tid & 31, w = tid >> 5;
    int incl = v;
    #pragma unroll
    for (int o = 1; o < 32; o <<= 1) {
        int t = __shfl_up_sync(0xffffffffu, incl, o);
        if (lane >= o) incl += t;
    }
    if (lane == 31) ws[w] = incl;
    __syncthreads();
    if (w == 0) {
        int s = ws[lane];
        int si = s;
        #pragma unroll
        for (int o = 1; o < 32; o <<= 1) {
            int t = __shfl_up_sync(0xffffffffu, si, o);
            if (lane >= o) si += t;
        }
        ws[lane] = si - s;
        if (lane == 31) g_bsum[b] = si;
    }
    __syncthreads();
    if (i < NN) g_off[i] = incl - v + ws[w];
}

__global__ void k_scan3() {
    const int b = blockIdx.x;
    __shared__ int boff;
    if (threadIdx.x == 0) {
        int s = 0;
        for (int i = 0; i < b; i++) s += g_bsum[i];
        boff = s;
    }
    __syncthreads();
    const int i = b * 1024 + threadIdx.x;
    if (i < NN) {
        const int v = g_off[i] + boff;
        g_off[i] = v;
        g_woff[i] = v;
    }
}

// ---------------------------------------------------------------------------
__global__ void k_scatter(const int* __restrict__ ei, const int* __restrict__ etypes) {
    const int e = blockIdx.x * blockDim.x + threadIdx.x;
    if (e >= EE) return;
    const int src = ei[e];
    const int d   = ei[EE + e];
    const int et  = etypes[e];
    const int pos = atomicAdd(&g_woff[d], 1);
    g_erec[pos] = ((long long)e << 32) | (unsigned)(src | (et << 16));
}

// ---------------------------------------------------------------------------
// Fused edge+aggregate. 64-thread blocks (2 warps), one warp per dst node.
// Depth-2 pipeline; per-half shfl butterfly for the attention ea-term;
// f32x2 packed accumulators.
// ---------------------------------------------------------------------------
struct Ebuf {
    long long rec;
    float4 va, vb, vc, vd;
    float  hmv;
    float2 asr;
};

__device__ __forceinline__ void fetch_edge(Ebuf& b, const long long* __restrict__ erecp,
                                           int idx, int c,
                                           const float* __restrict__ eattr, int lane) {
    b.rec = 0; b.hmv = 0.f; b.asr = make_float2(0.f, 0.f);
    b.va = b.vb = b.vc = b.vd = make_float4(0.f, 0.f, 0.f, 0.f);
    if (idx < c) {
        b.rec = __ldg(erecp + idx);
        const size_t e = (size_t)(b.rec >> 32);
        const int sp = (int)b.rec, src = sp & 0xFFFF;
        const float4* er = reinterpret_cast<const float4*>(&eattr[e * ED_]);
        b.va = __ldg(er); b.vb = __ldg(er + 1); b.vc = __ldg(er + 2); b.vd = __ldg(er + 3);
        b.hmv = __ldg(&g_hm[src * OUT_F + lane]);
        b.asr = *reinterpret_cast<const float2*>(&g_att[src * 4 + 2]);
    }
}

__global__ void __launch_bounds__(64) k_agg(
        const float* __restrict__ eattr, const float* __restrict__ etab,
        const float* __restrict__ eattr_W, const float* __restrict__ att_W,
        const float* __restrict__ lin_W, float* __restrict__ out) {
    __shared__ float lW2[EAE_ * OUT_F];              // lin_W rows 32..47
    __shared__ __align__(8) float cet[ET_ * 2];      // edge-type logit pairs

    const int tid  = threadIdx.x;
    const int lane = tid & 31;
    const int cl   = lane & 15;

    for (int i = tid; i < EAE_ * OUT_F; i += blockDim.x) lW2[i] = lin_W[OUT_F * OUT_F + i];
    if (tid < ET_ * 2) {
        const int et = tid >> 1, h = tid & 1;
        float s = 0.f;
        for (int j = 0; j < ETE_; j++)
            s += lrelu(etab[et * ETE_ + j]) * att_W[(64 + j) * 2 + h];
        cet[tid] = s;
    }
    __syncthreads();

    float Wr[ED_];
    #pragma unroll
    for (int k = 0; k < ED_; k++) Wr[k] = eattr_W[k * EAE_ + cl];
    // head for this lane's half: lower lanes head0, upper lanes head1
    const float awh = att_W[160 + cl * 2 + (lane >> 4)];

    const int n = blockIdx.x * (blockDim.x >> 5) + (tid >> 5);
    if (n >= NN) return;

    const int off = g_off[n], c = g_cnt[n];
    if (lane == 0) g_cnt[n] = 0;   // restore zero-invariant for next call
    const float2 adt = *reinterpret_cast<const float2*>(&g_att[n * 4]);
    const u64t adt01 = pk2(adt.x, adt.y);
    const bool lowhalf = (lane < 16);

    u64t acc = 0, wea = 0, dd = 0;   // packed {head0, head1}; bits 0 == 0.0f

    const long long* erecp = &g_erec[off];
    Ebuf b0, b1;
    fetch_edge(b0, erecp, 0, c, eattr, lane);
    fetch_edge(b1, erecp, 1, c, eattr, lane);

    #define PROC(b)                                                                   \
    {                                                                                 \
        float z = b.va.x * Wr[0]  + b.va.y * Wr[1]  + b.va.z * Wr[2]  + b.va.w * Wr[3]\
                + b.vb.x * Wr[4]  + b.vb.y * Wr[5]  + b.vb.z * Wr[6]  + b.vb.w * Wr[7]\
                + b.vc.x * Wr[8]  + b.vc.y * Wr[9]  + b.vc.z * Wr[10] + b.vc.w * Wr[11]\
                + b.vd.x * Wr[12] + b.vd.y * Wr[13] + b.vd.z * Wr[14] + b.vd.w * Wr[15];\
        const float ea = lrelu(z);                                                    \
        float ph = ea * awh;                                                          \
        ph += __shfl_xor_sync(0xffffffffu, ph, 8);                                    \
        ph += __shfl_xor_sync(0xffffffffu, ph, 4);                                    \
        ph += __shfl_xor_sync(0xffffffffu, ph, 2);                                    \
        ph += __shfl_xor_sync(0xffffffffu, ph, 1);                                    \
        const float po = __shfl_xor_sync(0xffffffffu, ph, 16);                        \
        const float p0 = lowhalf ? ph : po;                                           \
        const float p1 = lowhalf ? po : ph;                                           \
        const int   et = ((int)b.rec >> 16) & 3;                                      \
        const u64t cet01 = *reinterpret_cast<const u64t*>(&cet[et * 2]);              \
        const u64t l01 = add2(add2(adt01, pk2(b.asr.x, b.asr.y)),                     \
                              add2(cet01, pk2(p0, p1)));                              \
        float l0, l1; upk2(l01, l0, l1);                                              \
        const float a0 = __expf(lrelu(l0));                                           \
        const float a1 = __expf(lrelu(l1));                                           \
        const u64t a01 = pk2(a0, a1);                                                 \
        acc = fma2(a01, pk2(b.hmv, b.hmv), acc);                                      \
        wea = fma2(a01, pk2(ea, ea), wea);                                            \
        dd  = add2(dd, a01);                                                          \
    }

    int i = 0;
    for (; i + 1 < c; i += 2) {
        PROC(b0);
        fetch_edge(b0, erecp, i + 2, c, eattr, lane);
        PROC(b1);
        fetch_edge(b1, erecp, i + 3, c, eattr, lane);
    }
    if (i < c) PROC(b0);
    #undef PROC

    float acc0, acc1, wea0, wea1, d0, d1;
    upk2(acc, acc0, acc1); upk2(wea, wea0, wea1); upk2(dd, d0, d1);

    float m0 = acc0, m1 = acc1;
    #pragma unroll
    for (int k = 0; k < EAE_; k++) {
        m0 += __shfl_sync(0xffffffffu, wea0, k) * lW2[k * OUT_F + lane];
        m1 += __shfl_sync(0xffffffffu, wea1, k) * lW2[k * OUT_F + lane];
    }
    out[(size_t)n * 64 + lane]      = c ? fmaxf(m0 / d0, 0.f) : 0.f;
    out[(size_t)n * 64 + 32 + lane] = c ? fmaxf(m1 / d1, 0.f) : 0.f;
}

// ---------------------------------------------------------------------------
extern "C" void kernel_launch(void* const* d_in, const int* in_sizes, int n_in,
                              void* d_out, int out_size) {
    const float* x       = (const float*)d_in[0];
    const int*   ei      = (const int*)  d_in[1];
    const int*   ntypes  = (const int*)  d_in[2];
    const int*   etypes  = (const int*)  d_in[3];
    const float* eattr   = (const float*)d_in[4];
    const float* het_W   = (const float*)d_in[5];
    const float* het_b   = (const float*)d_in[6];
    const float* etab    = (const float*)d_in[7];
    const float* eattr_W = (const float*)d_in[8];
    const float* att_W   = (const float*)d_in[9];
    const float* lin_W   = (const float*)d_in[10];
    float* out = (float*)d_out;

    // g_cnt starts zeroed (device globals) and k_agg re-zeroes it each call.
    k_cnt<<<(EE + 255) / 256, 256>>>(ei);                         // launch 0

    dim3 gh(NT_, (NN + NPB - 1) / NPB);
    k_het<<<gh, 256>>>(x, ntypes, het_W, het_b, att_W, lin_W);    // launch 1

    const int NB = (NN + 1023) / 1024;
    k_scan1<<<NB, 1024>>>();                                      // launch 2
    k_scan3<<<NB, 1024>>>();                                      // launch 3

    k_scatter<<<(EE + 255) / 256, 256>>>(ei, etypes);             // launch 4

    k_agg<<<(NN + 1) / 2, 64>>>(eattr, etab, eattr_W, att_W, lin_W, out);  // launch 5
}

// round 9
// speedup vs baseline: 1.3153x; 1.3153x over previous
#include <cuda_runtime.h>

#define NN     50000
#define EE     1600000
#define IN_F   128
#define OUT_F  32
#define NT_    20
#define ET_    4
#define ETE_   16
#define EAE_   16
#define ED_    16
#define SLOPE  0.2f

// ---- scratch (device globals; allocation-free, zero-initialized) ----
__device__ float     g_hm[NN * OUT_F];   // 6.4 MB : h @ lin_W[0:32] (L2-resident)
__device__ float     g_att[NN * 4];      // 0.8 MB : {ai0, ai1, aj0, aj1}
__device__ long long g_erec[EE];         // 12.8 MB: dst-sorted {e, src|et<<16}
__device__ int       g_cnt[NN];          // zeroed by k_agg at end of every call
__device__ int       g_off[NN];
__device__ int       g_woff[NN];

__device__ __forceinline__ float lrelu(float v) { return v > 0.f ? v : SLOPE * v; }

// ---------------------------------------------------------------------------
// Merged HeteroLinear + dst-histogram.
//   blocks with blockIdx.x <  NT_ : het work for type blockIdx.x, chunk blockIdx.y
//   blocks with blockIdx.x >= NT_ : histogram over a strided edge chunk
// ---------------------------------------------------------------------------
#define NPB 1024
#define CNT_BX 128   // extra blocks in x for the histogram part
__global__ void k_hetcnt(const float* __restrict__ x, const int* __restrict__ ntypes,
                         const float* __restrict__ het_W, const float* __restrict__ het_b,
                         const float* __restrict__ att_W, const float* __restrict__ lin_W,
                         const int* __restrict__ ei) {
    if (blockIdx.x >= NT_) {
        // ---- histogram part ----
        const int cb = blockIdx.y * CNT_BX + (blockIdx.x - NT_);
        const int e  = cb * 256 + threadIdx.x;
        if (e < EE) atomicAdd(&g_cnt[ei[EE + e]], 1);
        return;
    }

    // ---- het part ----
    __shared__ float Ws[IN_F * OUT_F];
    __shared__ float bs[OUT_F];
    __shared__ float aWs[64 * 2];
    __shared__ float lWs[OUT_F * OUT_F];
    __shared__ int   list[NPB];
    __shared__ int   cnt;

    const int t    = blockIdx.x;
    const int base = blockIdx.y * NPB;
    const int tid  = threadIdx.x;

    for (int i = tid; i < IN_F * OUT_F; i += blockDim.x) Ws[i] = het_W[t * IN_F * OUT_F + i];
    for (int i = tid; i < OUT_F * OUT_F; i += blockDim.x) lWs[i] = lin_W[i];
    if (tid < 128)   aWs[tid] = att_W[tid];
    if (tid < OUT_F) bs[tid] = het_b[t * OUT_F + tid];
    if (tid == 0)    cnt = 0;
    __syncthreads();

    const int end = min(base + NPB, NN);
    for (int n = base + tid; n < end; n += blockDim.x)
        if (ntypes[n] == t) { int p = atomicAdd(&cnt, 1); list[p] = n; }
    __syncthreads();

    const int lane = tid & 31, warp = tid >> 5, nw = blockDim.x >> 5;
    for (int i = warp; i < cnt; i += nw) {
        const int n = list[i];
        const float* xr = x + (size_t)n * IN_F;
        float x0 = xr[lane], x1 = xr[32 + lane], x2 = xr[64 + lane], x3 = xr[96 + lane];
        float acc = bs[lane];
        #pragma unroll
        for (int k = 0; k < 32; k++) {
            acc += __shfl_sync(0xffffffffu, x0, k) * Ws[ k        * OUT_F + lane];
            acc += __shfl_sync(0xffffffffu, x1, k) * Ws[(32 + k)  * OUT_F + lane];
            acc += __shfl_sync(0xffffffffu, x2, k) * Ws[(64 + k)  * OUT_F + lane];
            acc += __shfl_sync(0xffffffffu, x3, k) * Ws[(96 + k)  * OUT_F + lane];
        }
        float ai0 = acc * aWs[lane * 2 + 0], ai1 = acc * aWs[lane * 2 + 1];
        float aj0 = acc * aWs[64 + lane * 2 + 0], aj1 = acc * aWs[64 + lane * 2 + 1];
        #pragma unroll
        for (int o = 16; o > 0; o >>= 1) {
            ai0 += __shfl_xor_sync(0xffffffffu, ai0, o);
            ai1 += __shfl_xor_sync(0xffffffffu, ai1, o);
            aj0 += __shfl_xor_sync(0xffffffffu, aj0, o);
            aj1 += __shfl_xor_sync(0xffffffffu, aj1, o);
        }
        float hm = 0.f;
        #pragma unroll
        for (int k = 0; k < 32; k++)
            hm += __shfl_sync(0xffffffffu, acc, k) * lWs[k * OUT_F + lane];
        g_hm[n * OUT_F + lane] = hm;
        if (lane == 0)
            *reinterpret_cast<float4*>(&g_att[n * 4]) = make_float4(ai0, ai1, aj0, aj1);
    }
}

// ---------------------------------------------------------------------------
// Single-block exclusive scan of g_cnt (49 sequential 1024-tiles with carry)
// ---------------------------------------------------------------------------
__global__ void k_scan() {
    __shared__ int ws[32];
    __shared__ int carry, tot;
    const int tid = threadIdx.x, lane = tid & 31, w = tid >> 5;
    if (tid == 0) carry = 0;
    __syncthreads();

    for (int base = 0; base < NN; base += 1024) {
        const int i = base + tid;
        int v = (i < NN) ? g_cnt[i] : 0;
        int incl = v;
        #pragma unroll
        for (int o = 1; o < 32; o <<= 1) {
            int t = __shfl_up_sync(0xffffffffu, incl, o);
            if (lane >= o) incl += t;
        }
        if (lane == 31) ws[w] = incl;
        __syncthreads();
        if (tid < 32) {
            int s = ws[tid];
            int si = s;
            #pragma unroll
            for (int o = 1; o < 32; o <<= 1) {
                int t = __shfl_up_sync(0xffffffffu, si, o);
                if (tid >= o) si += t;
            }
            ws[tid] = si - s;
            if (tid == 31) tot = si;
        }
        __syncthreads();
        const int excl = incl - v + ws[w] + carry;
        if (i < NN) { g_off[i] = excl; g_woff[i] = excl; }
        __syncthreads();
        if (tid == 0) carry += tot;
        __syncthreads();
    }
}

// ---------------------------------------------------------------------------
__global__ void k_scatter(const int* __restrict__ ei, const int* __restrict__ etypes) {
    const int e = blockIdx.x * blockDim.x + threadIdx.x;
    if (e >= EE) return;
    const int src = ei[e];
    const int d   = ei[EE + e];
    const int et  = etypes[e];
    const int pos = atomicAdd(&g_woff[d], 1);
    g_erec[pos] = ((long long)e << 32) | (unsigned)(src | (et << 16));
}

// ---------------------------------------------------------------------------
// Fused edge+aggregate (R5-proven shape): 256-thread blocks, one warp/node,
// depth-2 pipeline, plain float accumulators. Only change vs R5: 5-op
// per-half butterfly for the attention ea-term reduce.
// ---------------------------------------------------------------------------
struct Ebuf {
    long long rec;
    float4 va, vb, vc, vd;
    float  hmv;
    float2 asr;
};

__device__ __forceinline__ void fetch_edge(Ebuf& b, const long long* __restrict__ erecp,
                                           int idx, int c,
                                           const float* __restrict__ eattr, int lane) {
    b.rec = 0; b.hmv = 0.f; b.asr = make_float2(0.f, 0.f);
    b.va = b.vb = b.vc = b.vd = make_float4(0.f, 0.f, 0.f, 0.f);
    if (idx < c) {
        b.rec = __ldg(erecp + idx);
        const size_t e = (size_t)(b.rec >> 32);
        const int sp = (int)b.rec, src = sp & 0xFFFF;
        const float4* er = reinterpret_cast<const float4*>(&eattr[e * ED_]);
        b.va = __ldg(er); b.vb = __ldg(er + 1); b.vc = __ldg(er + 2); b.vd = __ldg(er + 3);
        b.hmv = __ldg(&g_hm[src * OUT_F + lane]);
        b.asr = *reinterpret_cast<const float2*>(&g_att[src * 4 + 2]);
    }
}

__global__ void __launch_bounds__(256) k_agg(
        const float* __restrict__ eattr, const float* __restrict__ etab,
        const float* __restrict__ eattr_W, const float* __restrict__ att_W,
        const float* __restrict__ lin_W, float* __restrict__ out) {
    __shared__ float lW2[EAE_ * OUT_F];  // lin_W rows 32..47
    __shared__ float cet[ET_ * 2];

    const int tid  = threadIdx.x;
    const int lane = tid & 31;
    const int cl   = lane & 15;

    for (int i = tid; i < EAE_ * OUT_F; i += blockDim.x) lW2[i] = lin_W[OUT_F * OUT_F + i];
    if (tid < ET_ * 2) {
        const int et = tid >> 1, h = tid & 1;
        float s = 0.f;
        for (int j = 0; j < ETE_; j++)
            s += lrelu(etab[et * ETE_ + j]) * att_W[(64 + j) * 2 + h];
        cet[tid] = s;
    }
    __syncthreads();

    float Wr[ED_];
    #pragma unroll
    for (int k = 0; k < ED_; k++) Wr[k] = eattr_W[k * EAE_ + cl];
    // lane's half computes its own head: lower=head0, upper=head1
    const float awh = att_W[160 + cl * 2 + (lane >> 4)];
    const bool lowhalf = (lane < 16);

    const int n = blockIdx.x * (blockDim.x >> 5) + (tid >> 5);
    if (n >= NN) return;

    const int off = g_off[n], c = g_cnt[n];
    if (lane == 0) g_cnt[n] = 0;   // restore zero-invariant for next call
    const float2 adt = *reinterpret_cast<const float2*>(&g_att[n * 4]);

    float acc0 = 0.f, acc1 = 0.f, wea0 = 0.f, wea1 = 0.f, d0 = 0.f, d1 = 0.f;

    const long long* erecp = &g_erec[off];
    Ebuf b0, b1;
    fetch_edge(b0, erecp, 0, c, eattr, lane);
    fetch_edge(b1, erecp, 1, c, eattr, lane);

    #define PROC(b)                                                                   \
    {                                                                                 \
        float z = b.va.x * Wr[0]  + b.va.y * Wr[1]  + b.va.z * Wr[2]  + b.va.w * Wr[3]\
                + b.vb.x * Wr[4]  + b.vb.y * Wr[5]  + b.vb.z * Wr[6]  + b.vb.w * Wr[7]\
                + b.vc.x * Wr[8]  + b.vc.y * Wr[9]  + b.vc.z * Wr[10] + b.vc.w * Wr[11]\
                + b.vd.x * Wr[12] + b.vd.y * Wr[13] + b.vd.z * Wr[14] + b.vd.w * Wr[15];\
        const float ea = lrelu(z);                                                    \
        float ph = ea * awh;                                                          \
        ph += __shfl_xor_sync(0xffffffffu, ph, 8);                                    \
        ph += __shfl_xor_sync(0xffffffffu, ph, 4);                                    \
        ph += __shfl_xor_sync(0xffffffffu, ph, 2);                                    \
        ph += __shfl_xor_sync(0xffffffffu, ph, 1);                                    \
        const float po = __shfl_xor_sync(0xffffffffu, ph, 16);                        \
        const float p0 = lowhalf ? ph : po;                                           \
        const float p1 = lowhalf ? po : ph;                                           \
        const int   et = ((int)b.rec >> 16) & 3;                                      \
        const float l0 = adt.x + b.asr.x + cet[et * 2 + 0] + p0;                      \
        const float l1 = adt.y + b.asr.y + cet[et * 2 + 1] + p1;                      \
        const float a0 = __expf(lrelu(l0));                                           \
        const float a1 = __expf(lrelu(l1));                                           \
        acc0 += a0 * b.hmv;  acc1 += a1 * b.hmv;                                      \
        wea0 += a0 * ea;     wea1 += a1 * ea;                                         \
        d0   += a0;          d1   += a1;                                              \
    }

    int i = 0;
    for (; i + 1 < c; i += 2) {
        PROC(b0);
        fetch_edge(b0, erecp, i + 2, c, eattr, lane);
        PROC(b1);
        fetch_edge(b1, erecp, i + 3, c, eattr, lane);
    }
    if (i < c) PROC(b0);
    #undef PROC

    float m0 = acc0, m1 = acc1;
    #pragma unroll
    for (int k = 0; k < EAE_; k++) {
        m0 += __shfl_sync(0xffffffffu, wea0, k) * lW2[k * OUT_F + lane];
        m1 += __shfl_sync(0xffffffffu, wea1, k) * lW2[k * OUT_F + lane];
    }
    out[(size_t)n * 64 + lane]      = c ? fmaxf(m0 / d0, 0.f) : 0.f;
    out[(size_t)n * 64 + 32 + lane] = c ? fmaxf(m1 / d1, 0.f) : 0.f;
}

// ---------------------------------------------------------------------------
extern "C" void kernel_launch(void* const* d_in, const int* in_sizes, int n_in,
                              void* d_out, int out_size) {
    const float* x       = (const float*)d_in[0];
    const int*   ei      = (const int*)  d_in[1];
    const int*   ntypes  = (const int*)  d_in[2];
    const int*   etypes  = (const int*)  d_in[3];
    const float* eattr   = (const float*)d_in[4];
    const float* het_W   = (const float*)d_in[5];
    const float* het_b   = (const float*)d_in[6];
    const float* etab    = (const float*)d_in[7];
    const float* eattr_W = (const float*)d_in[8];
    const float* att_W   = (const float*)d_in[9];
    const float* lin_W   = (const float*)d_in[10];
    float* out = (float*)d_out;

    // launch 0: het + dst-histogram (merged; g_cnt zero-invariant maintained by k_agg)
    dim3 gh(NT_ + CNT_BX, (NN + NPB - 1) / NPB);   // (148, 49)
    k_hetcnt<<<gh, 256>>>(x, ntypes, het_W, het_b, att_W, lin_W, ei);

    // launch 1: exclusive scan (single block, sequential tiles)
    k_scan<<<1, 1024>>>();

    // launch 2: dst-sorted scatter of compact edge records
    k_scatter<<<(EE + 255) / 256, 256>>>(ei, etypes);

    // launch 3: fused edge+aggregate (this is the launch ncu captures)
    k_agg<<<(NN * 32 + 255) / 256, 256>>>(eattr, etab, eattr_W, att_W, lin_W, out);
}